// round 2
// baseline (speedup 1.0000x reference)
#include <cuda_runtime.h>
#include <cuda_bf16.h>
#include <math.h>

// Problem constants
#define BB 4
#define LL 4096
#define DD 1024
#define RR 32
#define GG 256
#define MTOK (BB*LL)          // 16384 tokens
#define NSEG 8
#define SEG  (LL/NSEG)        // 512

// ---------------- scratch (static device memory; no allocations) ----------------
__device__ float g_h[MTOK * GG];        // 16 MB : relu(x@W1+b1)
__device__ float g_UV[MTOK * 64];       //  4 MB : cols 0..31 = U, 32..63 = V
__device__ float g_gateU[MTOK * RR];    //  2 MB : sigmoid(h@W2+b2) * U
__device__ float g_glob[MTOK * RR];     //  2 MB : local cumsum, then gate*U*S
__device__ float g_segsum[BB * NSEG * RR];
__device__ float g_segoff[BB * NSEG * RR];

// ======================================================================
// K1: h = relu(x @ W1 + b1)   (16384 x 1024) @ (1024 x 256)
// Classic 128x128x8 SGEMM, 256 threads, 8x8 per thread.
// ======================================================================
#define K1_BM 128
#define K1_BN 128
#define K1_BK 8
__global__ void __launch_bounds__(256) k1_gate_h(
    const float* __restrict__ A,      // x       (M x 1024)
    const float* __restrict__ W,      // gate_w1 (1024 x 256)
    const float* __restrict__ bias)   // gate_b1 (256)
{
    const int K = DD, N = GG;
    __shared__ float As[K1_BK][K1_BM];
    __shared__ float Bs[K1_BK][K1_BN];

    const int tid = threadIdx.x;
    const int bx = blockIdx.x;            // N tile (0..1)
    const int by = blockIdx.y;            // M tile (0..127)
    const int tx = tid & 15;              // 0..15 -> 8 cols each
    const int ty = tid >> 4;              // 0..15 -> 8 rows each

    const int aRow = tid >> 1;            // 0..127
    const int aCol = (tid & 1) * 4;       // 0 or 4
    const int bRow = tid >> 5;            // 0..7
    const int bCol = (tid & 31) * 4;      // 0..124

    const float* Aptr = A + (size_t)by * K1_BM * K;
    const float* Wptr = W + bx * K1_BN;

    float acc[8][8];
    #pragma unroll
    for (int i = 0; i < 8; i++)
        #pragma unroll
        for (int j = 0; j < 8; j++) acc[i][j] = 0.f;

    for (int k0 = 0; k0 < K; k0 += K1_BK) {
        float4 a4 = *(const float4*)(Aptr + (size_t)aRow * K + k0 + aCol);
        As[aCol + 0][aRow] = a4.x;
        As[aCol + 1][aRow] = a4.y;
        As[aCol + 2][aRow] = a4.z;
        As[aCol + 3][aRow] = a4.w;
        float4 b4 = *(const float4*)(Wptr + (size_t)(k0 + bRow) * N + bCol);
        *(float4*)&Bs[bRow][bCol] = b4;
        __syncthreads();

        #pragma unroll
        for (int kk = 0; kk < K1_BK; kk++) {
            float areg[8], breg[8];
            #pragma unroll
            for (int i = 0; i < 8; i++) areg[i] = As[kk][ty * 8 + i];
            #pragma unroll
            for (int j = 0; j < 8; j++) breg[j] = Bs[kk][tx * 8 + j];
            #pragma unroll
            for (int i = 0; i < 8; i++)
                #pragma unroll
                for (int j = 0; j < 8; j++)
                    acc[i][j] = fmaf(areg[i], breg[j], acc[i][j]);
        }
        __syncthreads();
    }

    #pragma unroll
    for (int i = 0; i < 8; i++) {
        int row = by * K1_BM + ty * 8 + i;
        #pragma unroll
        for (int j = 0; j < 8; j += 4) {
            int col = bx * K1_BN + tx * 8 + j;
            float4 v;
            v.x = fmaxf(acc[i][j + 0] + bias[col + 0], 0.f);
            v.y = fmaxf(acc[i][j + 1] + bias[col + 1], 0.f);
            v.z = fmaxf(acc[i][j + 2] + bias[col + 2], 0.f);
            v.w = fmaxf(acc[i][j + 3] + bias[col + 3], 0.f);
            *(float4*)&g_h[(size_t)row * N + col] = v;
        }
    }
}

// ======================================================================
// K2a: UV = x @ [U_w | V_w]   (16384 x 1024) @ (1024 x 64)
// 128x64x16 tiles, 256 threads, 8x4 per thread.
// ======================================================================
#define K2_BM 128
#define K2_BN 64
#define K2_BK 16
__global__ void __launch_bounds__(256) k2a_uv(
    const float* __restrict__ A,       // x
    const float* __restrict__ Uw,      // (1024 x 32)
    const float* __restrict__ Vw)      // (1024 x 32)
{
    const int K = DD;
    __shared__ float As[K2_BK][K2_BM];
    __shared__ float Bs[K2_BK][K2_BN];

    const int tid = threadIdx.x;
    const int by = blockIdx.x;           // M tile (0..127)
    const int tx = tid & 15;             // 0..15 -> 4 cols
    const int ty = tid >> 4;             // 0..15 -> 8 rows

    const int aRow = tid >> 2;           // 0..63
    const int aCol = (tid & 3) * 4;      // 0..12
    const int bRow = tid >> 4;           // 0..15
    const int bCol = (tid & 15) * 4;     // 0..60

    const float* Aptr = A + (size_t)by * K2_BM * K;

    float acc[8][4];
    #pragma unroll
    for (int i = 0; i < 8; i++)
        #pragma unroll
        for (int j = 0; j < 4; j++) acc[i][j] = 0.f;

    for (int k0 = 0; k0 < K; k0 += K2_BK) {
        #pragma unroll
        for (int hh = 0; hh < 2; hh++) {
            int r = aRow + hh * 64;
            float4 a4 = *(const float4*)(Aptr + (size_t)r * K + k0 + aCol);
            As[aCol + 0][r] = a4.x;
            As[aCol + 1][r] = a4.y;
            As[aCol + 2][r] = a4.z;
            As[aCol + 3][r] = a4.w;
        }
        const float* src = (bCol < 32)
            ? (Uw + (size_t)(k0 + bRow) * 32 + bCol)
            : (Vw + (size_t)(k0 + bRow) * 32 + (bCol - 32));
        *(float4*)&Bs[bRow][bCol] = *(const float4*)src;
        __syncthreads();

        #pragma unroll
        for (int kk = 0; kk < K2_BK; kk++) {
            float areg[8], breg[4];
            #pragma unroll
            for (int i = 0; i < 8; i++) areg[i] = As[kk][ty * 8 + i];
            #pragma unroll
            for (int j = 0; j < 4; j++) breg[j] = Bs[kk][tx * 4 + j];
            #pragma unroll
            for (int i = 0; i < 8; i++)
                #pragma unroll
                for (int j = 0; j < 4; j++)
                    acc[i][j] = fmaf(areg[i], breg[j], acc[i][j]);
        }
        __syncthreads();
    }

    #pragma unroll
    for (int i = 0; i < 8; i++) {
        int row = by * K2_BM + ty * 8 + i;
        int col = tx * 4;
        float4 v = make_float4(acc[i][0], acc[i][1], acc[i][2], acc[i][3]);
        *(float4*)&g_UV[(size_t)row * 64 + col] = v;
    }
}

// ======================================================================
// K2b: gate = sigmoid(h @ W2 + b2); gateU = gate * U
// Block: 8 tokens x 32 cols, 256 threads; h tile AND W2 staged in smem.
// ======================================================================
__global__ void __launch_bounds__(256) k2b_gate(
    const float* __restrict__ W2,      // (256 x 32)
    const float* __restrict__ b2)      // (32)
{
    __shared__ float hs[8][GG];
    __shared__ float w2s[GG * RR];     // 32 KB
    const int tid = threadIdx.x;
    const int tok0 = blockIdx.x * 8;

    const float4* src = (const float4*)(g_h + (size_t)tok0 * GG);
    #pragma unroll
    for (int i = 0; i < 2; i++)
        ((float4*)&hs[0][0])[tid + i * 256] = src[tid + i * 256];
    const float4* wsrc = (const float4*)W2;
    #pragma unroll
    for (int i = 0; i < 8; i++)
        ((float4*)w2s)[tid + i * 256] = wsrc[tid + i * 256];
    __syncthreads();

    const int t = tid >> 5;
    const int c = tid & 31;
    float acc = b2[c];
    #pragma unroll 8
    for (int k = 0; k < GG; k++)
        acc = fmaf(hs[t][k], w2s[k * 32 + c], acc);

    float gate = 1.f / (1.f + expf(-acc));
    int token = tok0 + t;
    g_gateU[(size_t)token * RR + c] = gate * g_UV[(size_t)token * 64 + c];
}

// ======================================================================
// K3a: segmented inclusive cumsum of V over L.
// Grid: B*NSEG blocks, 1024 threads (32 l-positions x 32 ranks per chunk).
// Writes local cumsum into g_glob and segment totals into g_segsum.
// ======================================================================
__global__ void __launch_bounds__(1024) k3a_scan()
{
    const int b   = blockIdx.x >> 3;
    const int seg = blockIdx.x & 7;
    __shared__ float buf[32][33];

    const int tid  = threadIdx.x;
    const int lane = tid & 31;
    const int warp = tid >> 5;
    const int l    = tid >> 5;
    const int r    = tid & 31;

    const float* Vb = g_UV + (size_t)(b * LL + seg * SEG) * 64 + 32;
    float*       Sb = g_glob + (size_t)(b * LL + seg * SEG) * RR;

    float carry = 0.f;
    for (int c = 0; c < SEG / 32; c++) {
        buf[l][r] = Vb[(size_t)(c * 32 + l) * 64 + r];
        __syncthreads();
        // warp `warp` scans rank `warp` over 32 l positions
        float v = buf[lane][warp];
        #pragma unroll
        for (int off = 1; off < 32; off <<= 1) {
            float n = __shfl_up_sync(0xffffffffu, v, off);
            if (lane >= off) v += n;
        }
        v += carry;
        carry = __shfl_sync(0xffffffffu, v, 31);
        buf[lane][warp] = v;
        __syncthreads();
        Sb[c * 1024 + tid] = buf[l][r];
        __syncthreads();
    }
    if (lane == 0)
        g_segsum[(b * NSEG + seg) * RR + warp] = carry;
}

// K3b: exclusive scan of segment totals (1 block, 128 threads = (b,r) pairs)
__global__ void k3b_segoff()
{
    int i = threadIdx.x;
    if (i < BB * RR) {
        int b = i >> 5, r = i & 31;
        float acc = 0.f;
        for (int s = 0; s < NSEG; s++) {
            g_segoff[(b * NSEG + s) * RR + r] = acc;
            acc += g_segsum[(b * NSEG + s) * RR + r];
        }
    }
}

// K3c: glob = gateU * (S_local + seg_offset)   (in place on g_glob)
__global__ void __launch_bounds__(256) k3c_finalize()
{
    int idx = blockIdx.x * 256 + threadIdx.x;     // 0 .. MTOK*RR-1
    int r     = idx & 31;
    int token = idx >> 5;
    int b     = token >> 12;
    int lpos  = token & (LL - 1);
    int seg   = lpos >> 9;
    float S = g_glob[idx] + g_segoff[(b * NSEG + seg) * RR + r];
    g_glob[idx] = g_gateU[idx] * S;
}

// ======================================================================
// K4: out = glob @ out_w + out_b + depthwise_conv3(x)
// Block: 32 tokens x full D, 256 threads, 4 d-columns/thread.
// out_w slice held in registers (32 x float4 per thread).
// ======================================================================
__global__ void __launch_bounds__(256) k4_out(
    const float* __restrict__ x,
    const float* __restrict__ conv_w,   // (1024 x 3)
    const float* __restrict__ out_w,    // (32 x 1024)
    const float* __restrict__ out_b,    // (1024)
    float* __restrict__ out)
{
    const int tid = threadIdx.x;
    const int token0 = blockIdx.x * 32;
    const int l0 = token0 & (LL - 1);
    const int d0 = tid * 4;

    float4 w[RR];
    #pragma unroll
    for (int rr = 0; rr < RR; rr++)
        w[rr] = *(const float4*)(out_w + (size_t)rr * DD + d0);

    float4 c0, c1, c2;
    c0.x = conv_w[(d0 + 0) * 3 + 0]; c1.x = conv_w[(d0 + 0) * 3 + 1]; c2.x = conv_w[(d0 + 0) * 3 + 2];
    c0.y = conv_w[(d0 + 1) * 3 + 0]; c1.y = conv_w[(d0 + 1) * 3 + 1]; c2.y = conv_w[(d0 + 1) * 3 + 2];
    c0.z = conv_w[(d0 + 2) * 3 + 0]; c1.z = conv_w[(d0 + 2) * 3 + 1]; c2.z = conv_w[(d0 + 2) * 3 + 2];
    c0.w = conv_w[(d0 + 3) * 3 + 0]; c1.w = conv_w[(d0 + 3) * 3 + 1]; c2.w = conv_w[(d0 + 3) * 3 + 2];
    float4 b4 = *(const float4*)(out_b + d0);

    for (int t = 0; t < 32; t++) {
        int token = token0 + t;
        int lpos = l0 + t;
        const float* xr = x + (size_t)token * DD + d0;
        float4 xc = *(const float4*)xr;
        float4 xm = (lpos > 0)      ? *(const float4*)(xr - DD) : make_float4(0.f, 0.f, 0.f, 0.f);
        float4 xp = (lpos < LL - 1) ? *(const float4*)(xr + DD) : make_float4(0.f, 0.f, 0.f, 0.f);

        float4 acc;
        acc.x = b4.x + c0.x * xm.x + c1.x * xc.x + c2.x * xp.x;
        acc.y = b4.y + c0.y * xm.y + c1.y * xc.y + c2.y * xp.y;
        acc.z = b4.z + c0.z * xm.z + c1.z * xc.z + c2.z * xp.z;
        acc.w = b4.w + c0.w * xm.w + c1.w * xc.w + c2.w * xp.w;

        const float* gptr = g_glob + (size_t)token * RR;
        #pragma unroll
        for (int rr = 0; rr < RR; rr++) {
            float g = __ldg(gptr + rr);
            acc.x = fmaf(g, w[rr].x, acc.x);
            acc.y = fmaf(g, w[rr].y, acc.y);
            acc.z = fmaf(g, w[rr].z, acc.z);
            acc.w = fmaf(g, w[rr].w, acc.w);
        }
        *(float4*)(out + (size_t)token * DD + d0) = acc;
    }
}

// ======================================================================
extern "C" void kernel_launch(void* const* d_in, const int* in_sizes, int n_in,
                              void* d_out, int out_size)
{
    const float* x       = (const float*)d_in[0];
    const float* gate_w1 = (const float*)d_in[1];
    const float* gate_b1 = (const float*)d_in[2];
    const float* gate_w2 = (const float*)d_in[3];
    const float* gate_b2 = (const float*)d_in[4];
    const float* U_w     = (const float*)d_in[5];
    const float* V_w     = (const float*)d_in[6];
    const float* conv_w  = (const float*)d_in[7];
    const float* out_w   = (const float*)d_in[8];
    const float* out_b   = (const float*)d_in[9];
    float* out = (float*)d_out;

    // K1: h = relu(x@W1+b1)
    k1_gate_h<<<dim3(GG / K1_BN, MTOK / K1_BM), 256>>>(x, gate_w1, gate_b1);
    // K2a: UV = x@[Uw|Vw]
    k2a_uv<<<MTOK / K2_BM, 256>>>(x, U_w, V_w);
    // K2b: gateU
    k2b_gate<<<MTOK / 8, 256>>>(gate_w2, gate_b2);
    // K3: segmented cumsum + finalize glob
    k3a_scan<<<BB * NSEG, 1024>>>();
    k3b_segoff<<<1, 128>>>();
    k3c_finalize<<<(MTOK * RR) / 256, 256>>>();
    // K4: output
    k4_out<<<MTOK / 32, 256>>>(x, conv_w, out_w, out_b, out);
}

// round 3
// speedup vs baseline: 1.6418x; 1.6418x over previous
#include <cuda_runtime.h>
#include <cuda_bf16.h>
#include <math.h>

// Problem constants
#define BB 4
#define LL 4096
#define DD 1024
#define RR 32
#define GG 256
#define MTOK (BB*LL)          // 16384 tokens
#define NSEG 32
#define SEG  (LL/NSEG)        // 128

// ---------------- scratch (static device memory; no allocations) ----------------
__device__ float g_h[MTOK * GG];        // 16 MB : relu(x@W1+b1)
__device__ float g_UV[MTOK * 64];       //  4 MB : cols 0..31 = U, 32..63 = V
__device__ float g_gateU[MTOK * RR];    //  2 MB : sigmoid(h@W2+b2) * U
__device__ float g_glob[MTOK * RR];     //  2 MB : local cumsum, then gate*U*S
__device__ float g_segsum[BB * NSEG * RR];
__device__ float g_segoff[BB * NSEG * RR];

// ---------------- tf32 helpers ----------------
__device__ __forceinline__ unsigned f2tf32(float f) {
    unsigned r;
    asm("cvt.rna.tf32.f32 %0, %1;" : "=r"(r) : "f"(f));
    return r;
}

__device__ __forceinline__ void mma_tf32(float* d, const unsigned* a, const unsigned* b) {
    asm volatile(
        "mma.sync.aligned.m16n8k8.row.col.f32.tf32.tf32.f32 "
        "{%0,%1,%2,%3}, {%4,%5,%6,%7}, {%8,%9}, {%0,%1,%2,%3};"
        : "+f"(d[0]), "+f"(d[1]), "+f"(d[2]), "+f"(d[3])
        : "r"(a[0]), "r"(a[1]), "r"(a[2]), "r"(a[3]), "r"(b[0]), "r"(b[1]));
}

// ======================================================================
// K1: h = relu(x @ W1 + b1)   (16384 x 1024) @ (1024 x 256), TF32 mma
// Block 128x128x32, 8 warps (2x4), warp tile 64x32 (4 m-atoms x 4 n-atoms)
// ======================================================================
#define T1_APAD 36
#define T1_BPAD 136
__global__ void __launch_bounds__(256) k1_tf32(
    const float* __restrict__ A,      // x       (M x 1024)
    const float* __restrict__ W,      // gate_w1 (1024 x 256)
    const float* __restrict__ bias)   // gate_b1 (256)
{
    const int K = DD, N = GG;
    __shared__ float As[128 * T1_APAD];
    __shared__ float Bs[32 * T1_BPAD];

    const int tid  = threadIdx.x;
    const int bx   = blockIdx.x;           // N tile (0..1)
    const int by   = blockIdx.y;           // M tile (0..127)
    const int wid  = tid >> 5;
    const int lane = tid & 31;
    const int g    = lane >> 2;            // 0..7
    const int tig  = lane & 3;             // 0..3
    const int warpM = wid >> 2;            // 0..1 -> 64 rows
    const int warpN = wid & 3;             // 0..3 -> 32 cols

    const float* Aptr = A + (size_t)by * 128 * K;
    const float* Wptr = W + bx * 128;

    float acc[4][4][4];
    #pragma unroll
    for (int ma = 0; ma < 4; ma++)
        #pragma unroll
        for (int na = 0; na < 4; na++)
            #pragma unroll
            for (int i = 0; i < 4; i++) acc[ma][na][i] = 0.f;

    for (int k0 = 0; k0 < K; k0 += 32) {
        // load A tile: 128 rows x 32 k = 1024 float4, 4 per thread
        #pragma unroll
        for (int i = 0; i < 4; i++) {
            int idx = tid + i * 256;
            int row = idx >> 3;
            int c4  = (idx & 7) * 4;
            float4 v = *(const float4*)(Aptr + (size_t)row * K + k0 + c4);
            *(float4*)&As[row * T1_APAD + c4] = v;
        }
        // load B tile: 32 k-rows x 128 n = 1024 float4, 4 per thread
        #pragma unroll
        for (int i = 0; i < 4; i++) {
            int idx = tid + i * 256;
            int krow = idx >> 5;
            int c4   = (idx & 31) * 4;
            float4 v = *(const float4*)(Wptr + (size_t)(k0 + krow) * N + c4);
            *(float4*)&Bs[krow * T1_BPAD + c4] = v;
        }
        __syncthreads();

        #pragma unroll
        for (int ks = 0; ks < 4; ks++) {
            int kb = ks * 8;
            unsigned afr[4][4], bfr[4][2];
            #pragma unroll
            for (int ma = 0; ma < 4; ma++) {
                int r0 = warpM * 64 + ma * 16;
                afr[ma][0] = f2tf32(As[(r0 + g)     * T1_APAD + kb + tig]);
                afr[ma][1] = f2tf32(As[(r0 + g + 8) * T1_APAD + kb + tig]);
                afr[ma][2] = f2tf32(As[(r0 + g)     * T1_APAD + kb + tig + 4]);
                afr[ma][3] = f2tf32(As[(r0 + g + 8) * T1_APAD + kb + tig + 4]);
            }
            #pragma unroll
            for (int na = 0; na < 4; na++) {
                int c0 = warpN * 32 + na * 8;
                bfr[na][0] = f2tf32(Bs[(kb + tig)     * T1_BPAD + c0 + g]);
                bfr[na][1] = f2tf32(Bs[(kb + tig + 4) * T1_BPAD + c0 + g]);
            }
            #pragma unroll
            for (int ma = 0; ma < 4; ma++)
                #pragma unroll
                for (int na = 0; na < 4; na++)
                    mma_tf32(acc[ma][na], afr[ma], bfr[na]);
        }
        __syncthreads();
    }

    // epilogue: bias + relu, write float2 pairs
    #pragma unroll
    for (int ma = 0; ma < 4; ma++) {
        int rbase = by * 128 + warpM * 64 + ma * 16;
        #pragma unroll
        for (int na = 0; na < 4; na++) {
            int col = bx * 128 + warpN * 32 + na * 8 + tig * 2;
            float b0 = __ldg(bias + col), b1 = __ldg(bias + col + 1);
            float2 v;
            v.x = fmaxf(acc[ma][na][0] + b0, 0.f);
            v.y = fmaxf(acc[ma][na][1] + b1, 0.f);
            *(float2*)&g_h[(size_t)(rbase + g) * GG + col] = v;
            v.x = fmaxf(acc[ma][na][2] + b0, 0.f);
            v.y = fmaxf(acc[ma][na][3] + b1, 0.f);
            *(float2*)&g_h[(size_t)(rbase + g + 8) * GG + col] = v;
        }
    }
}

// ======================================================================
// K2a: UV = x @ [U_w | V_w]  (16384 x 1024) @ (1024 x 64), TF32 mma
// Block 64x64x32, 8 warps (2x4), warp tile 32x16 (2 m-atoms x 2 n-atoms)
// ======================================================================
#define T2_APAD 36
#define T2_BPAD 72
__global__ void __launch_bounds__(256) k2a_tf32(
    const float* __restrict__ A,       // x
    const float* __restrict__ Uw,      // (1024 x 32)
    const float* __restrict__ Vw)      // (1024 x 32)
{
    const int K = DD;
    __shared__ float As[64 * T2_APAD];
    __shared__ float Bs[32 * T2_BPAD];

    const int tid  = threadIdx.x;
    const int by   = blockIdx.x;           // 0..255
    const int wid  = tid >> 5;
    const int lane = tid & 31;
    const int g    = lane >> 2;
    const int tig  = lane & 3;
    const int warpM = wid >> 2;            // 0..1 -> 32 rows
    const int warpN = wid & 3;             // 0..3 -> 16 cols

    const float* Aptr = A + (size_t)by * 64 * K;

    float acc[2][2][4];
    #pragma unroll
    for (int ma = 0; ma < 2; ma++)
        #pragma unroll
        for (int na = 0; na < 2; na++)
            #pragma unroll
            for (int i = 0; i < 4; i++) acc[ma][na][i] = 0.f;

    for (int k0 = 0; k0 < K; k0 += 32) {
        // A tile: 64 x 32 = 512 float4, 2 per thread
        #pragma unroll
        for (int i = 0; i < 2; i++) {
            int idx = tid + i * 256;
            int row = idx >> 3;
            int c4  = (idx & 7) * 4;
            float4 v = *(const float4*)(Aptr + (size_t)row * K + k0 + c4);
            *(float4*)&As[row * T2_APAD + c4] = v;
        }
        // B tile: 32 k-rows x 64 = 512 float4, 2 per thread
        #pragma unroll
        for (int i = 0; i < 2; i++) {
            int idx = tid + i * 256;
            int krow = idx >> 4;
            int c4   = (idx & 15) * 4;
            const float* src = (c4 < 32)
                ? (Uw + (size_t)(k0 + krow) * 32 + c4)
                : (Vw + (size_t)(k0 + krow) * 32 + (c4 - 32));
            *(float4*)&Bs[krow * T2_BPAD + c4] = *(const float4*)src;
        }
        __syncthreads();

        #pragma unroll
        for (int ks = 0; ks < 4; ks++) {
            int kb = ks * 8;
            unsigned afr[2][4], bfr[2][2];
            #pragma unroll
            for (int ma = 0; ma < 2; ma++) {
                int r0 = warpM * 32 + ma * 16;
                afr[ma][0] = f2tf32(As[(r0 + g)     * T2_APAD + kb + tig]);
                afr[ma][1] = f2tf32(As[(r0 + g + 8) * T2_APAD + kb + tig]);
                afr[ma][2] = f2tf32(As[(r0 + g)     * T2_APAD + kb + tig + 4]);
                afr[ma][3] = f2tf32(As[(r0 + g + 8) * T2_APAD + kb + tig + 4]);
            }
            #pragma unroll
            for (int na = 0; na < 2; na++) {
                int c0 = warpN * 16 + na * 8;
                bfr[na][0] = f2tf32(Bs[(kb + tig)     * T2_BPAD + c0 + g]);
                bfr[na][1] = f2tf32(Bs[(kb + tig + 4) * T2_BPAD + c0 + g]);
            }
            #pragma unroll
            for (int ma = 0; ma < 2; ma++)
                #pragma unroll
                for (int na = 0; na < 2; na++)
                    mma_tf32(acc[ma][na], afr[ma], bfr[na]);
        }
        __syncthreads();
    }

    #pragma unroll
    for (int ma = 0; ma < 2; ma++) {
        int rbase = by * 64 + warpM * 32 + ma * 16;
        #pragma unroll
        for (int na = 0; na < 2; na++) {
            int col = warpN * 16 + na * 8 + tig * 2;
            float2 v;
            v.x = acc[ma][na][0]; v.y = acc[ma][na][1];
            *(float2*)&g_UV[(size_t)(rbase + g) * 64 + col] = v;
            v.x = acc[ma][na][2]; v.y = acc[ma][na][3];
            *(float2*)&g_UV[(size_t)(rbase + g + 8) * 64 + col] = v;
        }
    }
}

// ======================================================================
// K2b: gate = sigmoid(h @ W2 + b2); gateU = gate * U
// Block: 8 tokens x 32 cols, 256 threads; h tile AND W2 staged in smem.
// ======================================================================
__global__ void __launch_bounds__(256) k2b_gate(
    const float* __restrict__ W2,      // (256 x 32)
    const float* __restrict__ b2)      // (32)
{
    __shared__ float hs[8][GG];
    __shared__ float w2s[GG * RR];     // 32 KB
    const int tid = threadIdx.x;
    const int tok0 = blockIdx.x * 8;

    const float4* src = (const float4*)(g_h + (size_t)tok0 * GG);
    #pragma unroll
    for (int i = 0; i < 2; i++)
        ((float4*)&hs[0][0])[tid + i * 256] = src[tid + i * 256];
    const float4* wsrc = (const float4*)W2;
    #pragma unroll
    for (int i = 0; i < 8; i++)
        ((float4*)w2s)[tid + i * 256] = wsrc[tid + i * 256];
    __syncthreads();

    const int t = tid >> 5;
    const int c = tid & 31;
    float acc = b2[c];
    #pragma unroll 8
    for (int k = 0; k < GG; k++)
        acc = fmaf(hs[t][k], w2s[k * 32 + c], acc);

    float gate = 1.f / (1.f + expf(-acc));
    int token = tok0 + t;
    g_gateU[(size_t)token * RR + c] = gate * g_UV[(size_t)token * 64 + c];
}

// ======================================================================
// K3a: segmented inclusive cumsum of V over L.
// Grid: B*NSEG blocks, 1024 threads (32 l-positions x 32 ranks per chunk).
// ======================================================================
__global__ void __launch_bounds__(1024) k3a_scan()
{
    const int b   = blockIdx.x >> 5;      // NSEG = 32
    const int seg = blockIdx.x & 31;
    __shared__ float buf[32][33];

    const int tid  = threadIdx.x;
    const int lane = tid & 31;
    const int warp = tid >> 5;
    const int l    = tid >> 5;
    const int r    = tid & 31;

    const float* Vb = g_UV + (size_t)(b * LL + seg * SEG) * 64 + 32;
    float*       Sb = g_glob + (size_t)(b * LL + seg * SEG) * RR;

    float carry = 0.f;
    for (int c = 0; c < SEG / 32; c++) {
        buf[l][r] = Vb[(size_t)(c * 32 + l) * 64 + r];
        __syncthreads();
        float v = buf[lane][warp];
        #pragma unroll
        for (int off = 1; off < 32; off <<= 1) {
            float n = __shfl_up_sync(0xffffffffu, v, off);
            if (lane >= off) v += n;
        }
        v += carry;
        carry = __shfl_sync(0xffffffffu, v, 31);
        buf[lane][warp] = v;
        __syncthreads();
        Sb[c * 1024 + tid] = buf[l][r];
        __syncthreads();
    }
    if (lane == 0)
        g_segsum[(b * NSEG + seg) * RR + warp] = carry;
}

// K3b: exclusive scan of segment totals (1 block, 128 threads = (b,r) pairs)
__global__ void k3b_segoff()
{
    int i = threadIdx.x;
    if (i < BB * RR) {
        int b = i >> 5, r = i & 31;
        float acc = 0.f;
        for (int s = 0; s < NSEG; s++) {
            g_segoff[(b * NSEG + s) * RR + r] = acc;
            acc += g_segsum[(b * NSEG + s) * RR + r];
        }
    }
}

// K3c: glob = gateU * (S_local + seg_offset)   (in place on g_glob)
__global__ void __launch_bounds__(256) k3c_finalize()
{
    int idx = blockIdx.x * 256 + threadIdx.x;     // 0 .. MTOK*RR-1
    int r     = idx & 31;
    int token = idx >> 5;
    int b     = token >> 12;
    int lpos  = token & (LL - 1);
    int seg   = lpos / SEG;
    float S = g_glob[idx] + g_segoff[(b * NSEG + seg) * RR + r];
    g_glob[idx] = g_gateU[idx] * S;
}

// ======================================================================
// K4: out = glob @ out_w + out_b + depthwise_conv3(x)
// Block: 32 tokens x full D, 256 threads, 4 d-columns/thread.
// ======================================================================
__global__ void __launch_bounds__(256) k4_out(
    const float* __restrict__ x,
    const float* __restrict__ conv_w,   // (1024 x 3)
    const float* __restrict__ out_w,    // (32 x 1024)
    const float* __restrict__ out_b,    // (1024)
    float* __restrict__ out)
{
    const int tid = threadIdx.x;
    const int token0 = blockIdx.x * 32;
    const int l0 = token0 & (LL - 1);
    const int d0 = tid * 4;

    float4 w[RR];
    #pragma unroll
    for (int rr = 0; rr < RR; rr++)
        w[rr] = *(const float4*)(out_w + (size_t)rr * DD + d0);

    float4 c0, c1, c2;
    c0.x = conv_w[(d0 + 0) * 3 + 0]; c1.x = conv_w[(d0 + 0) * 3 + 1]; c2.x = conv_w[(d0 + 0) * 3 + 2];
    c0.y = conv_w[(d0 + 1) * 3 + 0]; c1.y = conv_w[(d0 + 1) * 3 + 1]; c2.y = conv_w[(d0 + 1) * 3 + 2];
    c0.z = conv_w[(d0 + 2) * 3 + 0]; c1.z = conv_w[(d0 + 2) * 3 + 1]; c2.z = conv_w[(d0 + 2) * 3 + 2];
    c0.w = conv_w[(d0 + 3) * 3 + 0]; c1.w = conv_w[(d0 + 3) * 3 + 1]; c2.w = conv_w[(d0 + 3) * 3 + 2];
    float4 b4 = *(const float4*)(out_b + d0);

    for (int t = 0; t < 32; t++) {
        int token = token0 + t;
        int lpos = l0 + t;
        const float* xr = x + (size_t)token * DD + d0;
        float4 xc = *(const float4*)xr;
        float4 xm = (lpos > 0)      ? *(const float4*)(xr - DD) : make_float4(0.f, 0.f, 0.f, 0.f);
        float4 xp = (lpos < LL - 1) ? *(const float4*)(xr + DD) : make_float4(0.f, 0.f, 0.f, 0.f);

        float4 acc;
        acc.x = b4.x + c0.x * xm.x + c1.x * xc.x + c2.x * xp.x;
        acc.y = b4.y + c0.y * xm.y + c1.y * xc.y + c2.y * xp.y;
        acc.z = b4.z + c0.z * xm.z + c1.z * xc.z + c2.z * xp.z;
        acc.w = b4.w + c0.w * xm.w + c1.w * xc.w + c2.w * xp.w;

        const float* gptr = g_glob + (size_t)token * RR;
        #pragma unroll
        for (int rr = 0; rr < RR; rr++) {
            float g = __ldg(gptr + rr);
            acc.x = fmaf(g, w[rr].x, acc.x);
            acc.y = fmaf(g, w[rr].y, acc.y);
            acc.z = fmaf(g, w[rr].z, acc.z);
            acc.w = fmaf(g, w[rr].w, acc.w);
        }
        *(float4*)(out + (size_t)token * DD + d0) = acc;
    }
}

// ======================================================================
extern "C" void kernel_launch(void* const* d_in, const int* in_sizes, int n_in,
                              void* d_out, int out_size)
{
    const float* x       = (const float*)d_in[0];
    const float* gate_w1 = (const float*)d_in[1];
    const float* gate_b1 = (const float*)d_in[2];
    const float* gate_w2 = (const float*)d_in[3];
    const float* gate_b2 = (const float*)d_in[4];
    const float* U_w     = (const float*)d_in[5];
    const float* V_w     = (const float*)d_in[6];
    const float* conv_w  = (const float*)d_in[7];
    const float* out_w   = (const float*)d_in[8];
    const float* out_b   = (const float*)d_in[9];
    float* out = (float*)d_out;

    // K1: h = relu(x@W1+b1)  (tf32 tensor cores)
    k1_tf32<<<dim3(GG / 128, MTOK / 128), 256>>>(x, gate_w1, gate_b1);
    // K2a: UV = x@[Uw|Vw]    (tf32 tensor cores)
    k2a_tf32<<<MTOK / 64, 256>>>(x, U_w, V_w);
    // K2b: gateU
    k2b_gate<<<MTOK / 8, 256>>>(gate_w2, gate_b2);
    // K3: segmented cumsum + finalize glob
    k3a_scan<<<BB * NSEG, 1024>>>();
    k3b_segoff<<<1, 128>>>();
    k3c_finalize<<<(MTOK * RR) / 256, 256>>>();
    // K4: output
    k4_out<<<MTOK / 32, 256>>>(x, conv_w, out_w, out_b, out);
}

// round 6
// speedup vs baseline: 2.5829x; 1.5732x over previous
#include <cuda_runtime.h>
#include <cuda_bf16.h>
#include <math.h>

// Problem constants
#define BB 4
#define LL 4096
#define DD 1024
#define RR 32
#define GG 256
#define MTOK (BB*LL)          // 16384 tokens
#define NSEG 32
#define SEG  (LL/NSEG)        // 128

// ---------------- scratch (static device memory; no allocations) ----------------
__device__ float g_h[MTOK * GG];        // 16 MB : relu(x@W1+b1)
__device__ float g_UV[MTOK * 64];       //  4 MB : cols 0..31 = U, 32..63 = V
__device__ float g_gateU[MTOK * RR];    //  2 MB : sigmoid(h@W2+b2) * U
__device__ float g_glob[MTOK * RR];     //  2 MB : local (per-segment) cumsum of V
__device__ float g_segsum[BB * NSEG * RR];
__device__ float g_segoff[BB * NSEG * RR];

// ---------------- tf32 helpers ----------------
__device__ __forceinline__ unsigned f2tf32(float f) {
    unsigned r;
    asm("cvt.rna.tf32.f32 %0, %1;" : "=r"(r) : "f"(f));
    return r;
}

__device__ __forceinline__ void mma_tf32(float* d, const unsigned* a, const unsigned* b) {
    asm volatile(
        "mma.sync.aligned.m16n8k8.row.col.f32.tf32.tf32.f32 "
        "{%0,%1,%2,%3}, {%4,%5,%6,%7}, {%8,%9}, {%0,%1,%2,%3};"
        : "+f"(d[0]), "+f"(d[1]), "+f"(d[2]), "+f"(d[3])
        : "r"(a[0]), "r"(a[1]), "r"(a[2]), "r"(a[3]), "r"(b[0]), "r"(b[1]));
}

// ======================================================================
// K1: h = relu(x @ W1 + b1)   (16384 x 1024) @ (1024 x 256), TF32 mma
// Block 128x128x32, 8 warps (2x4), warp tile 64x32.
// tf32 stored in smem (cvt once); register prefetch of next k-tile.
// ======================================================================
#define T1_APAD 36
#define T1_BPAD 136
__global__ void __launch_bounds__(256) k1_tf32(
    const float* __restrict__ A,      // x       (M x 1024)
    const float* __restrict__ W,      // gate_w1 (1024 x 256)
    const float* __restrict__ bias)   // gate_b1 (256)
{
    const int K = DD, N = GG;
    __shared__ unsigned As[128 * T1_APAD];
    __shared__ unsigned Bs[32 * T1_BPAD];

    const int tid  = threadIdx.x;
    const int bx   = blockIdx.x;           // N tile (0..1)
    const int by   = blockIdx.y;           // M tile (0..127)
    const int wid  = tid >> 5;
    const int lane = tid & 31;
    const int g    = lane >> 2;            // 0..7
    const int tig  = lane & 3;             // 0..3
    const int warpM = wid >> 2;            // 0..1 -> 64 rows
    const int warpN = wid & 3;             // 0..3 -> 32 cols

    const float* Aptr = A + (size_t)by * 128 * K;
    const float* Wptr = W + bx * 128;

    // per-thread load coordinates
    const int aRow = tid >> 3;             // 0..31 (x4 batches -> 128 rows)
    const int aC4  = (tid & 7) * 4;
    const int bKr  = tid >> 5;             // 0..7  (x4 batches -> 32 krows)
    const int bC4  = (tid & 31) * 4;

    float acc[4][4][4];
    #pragma unroll
    for (int ma = 0; ma < 4; ma++)
        #pragma unroll
        for (int na = 0; na < 4; na++)
            #pragma unroll
            for (int i = 0; i < 4; i++) acc[ma][na][i] = 0.f;

    float4 pa[4], pb[4];
    // prologue loads (k0 = 0)
    #pragma unroll
    for (int i = 0; i < 4; i++)
        pa[i] = *(const float4*)(Aptr + (size_t)(aRow + i * 32) * K + aC4);
    #pragma unroll
    for (int i = 0; i < 4; i++)
        pb[i] = *(const float4*)(Wptr + (size_t)(bKr + i * 8) * N + bC4);

    for (int k0 = 0; k0 < K; k0 += 32) {
        // store current tile with cvt
        #pragma unroll
        for (int i = 0; i < 4; i++) {
            int row = aRow + i * 32;
            As[row * T1_APAD + aC4 + 0] = f2tf32(pa[i].x);
            As[row * T1_APAD + aC4 + 1] = f2tf32(pa[i].y);
            As[row * T1_APAD + aC4 + 2] = f2tf32(pa[i].z);
            As[row * T1_APAD + aC4 + 3] = f2tf32(pa[i].w);
        }
        #pragma unroll
        for (int i = 0; i < 4; i++) {
            int kr = bKr + i * 8;
            Bs[kr * T1_BPAD + bC4 + 0] = f2tf32(pb[i].x);
            Bs[kr * T1_BPAD + bC4 + 1] = f2tf32(pb[i].y);
            Bs[kr * T1_BPAD + bC4 + 2] = f2tf32(pb[i].z);
            Bs[kr * T1_BPAD + bC4 + 3] = f2tf32(pb[i].w);
        }
        __syncthreads();

        // prefetch next tile (overlaps with mma below)
        if (k0 + 32 < K) {
            #pragma unroll
            for (int i = 0; i < 4; i++)
                pa[i] = *(const float4*)(Aptr + (size_t)(aRow + i * 32) * K + (k0 + 32) + aC4);
            #pragma unroll
            for (int i = 0; i < 4; i++)
                pb[i] = *(const float4*)(Wptr + (size_t)(k0 + 32 + bKr + i * 8) * N + bC4);
        }

        #pragma unroll
        for (int ks = 0; ks < 4; ks++) {
            int kb = ks * 8;
            unsigned afr[4][4], bfr[4][2];
            #pragma unroll
            for (int ma = 0; ma < 4; ma++) {
                int r0 = warpM * 64 + ma * 16;
                afr[ma][0] = As[(r0 + g)     * T1_APAD + kb + tig];
                afr[ma][1] = As[(r0 + g + 8) * T1_APAD + kb + tig];
                afr[ma][2] = As[(r0 + g)     * T1_APAD + kb + tig + 4];
                afr[ma][3] = As[(r0 + g + 8) * T1_APAD + kb + tig + 4];
            }
            #pragma unroll
            for (int na = 0; na < 4; na++) {
                int c0 = warpN * 32 + na * 8;
                bfr[na][0] = Bs[(kb + tig)     * T1_BPAD + c0 + g];
                bfr[na][1] = Bs[(kb + tig + 4) * T1_BPAD + c0 + g];
            }
            #pragma unroll
            for (int ma = 0; ma < 4; ma++)
                #pragma unroll
                for (int na = 0; na < 4; na++)
                    mma_tf32(acc[ma][na], afr[ma], bfr[na]);
        }
        __syncthreads();
    }

    // epilogue: bias + relu
    #pragma unroll
    for (int ma = 0; ma < 4; ma++) {
        int rbase = by * 128 + warpM * 64 + ma * 16;
        #pragma unroll
        for (int na = 0; na < 4; na++) {
            int col = bx * 128 + warpN * 32 + na * 8 + tig * 2;
            float b0 = __ldg(bias + col), b1 = __ldg(bias + col + 1);
            float2 v;
            v.x = fmaxf(acc[ma][na][0] + b0, 0.f);
            v.y = fmaxf(acc[ma][na][1] + b1, 0.f);
            *(float2*)&g_h[(size_t)(rbase + g) * GG + col] = v;
            v.x = fmaxf(acc[ma][na][2] + b0, 0.f);
            v.y = fmaxf(acc[ma][na][3] + b1, 0.f);
            *(float2*)&g_h[(size_t)(rbase + g + 8) * GG + col] = v;
        }
    }
}

// ======================================================================
// K2a: UV = x @ [U_w | V_w]  (16384 x 1024) @ (1024 x 64), TF32 mma
// Block 64x64x32, 8 warps (2x4), warp tile 32x16.
// ======================================================================
#define T2_APAD 36
#define T2_BPAD 72
__global__ void __launch_bounds__(256) k2a_tf32(
    const float* __restrict__ A,       // x
    const float* __restrict__ Uw,      // (1024 x 32)
    const float* __restrict__ Vw)      // (1024 x 32)
{
    const int K = DD;
    __shared__ float As[64 * T2_APAD];
    __shared__ float Bs[32 * T2_BPAD];

    const int tid  = threadIdx.x;
    const int by   = blockIdx.x;           // 0..255
    const int wid  = tid >> 5;
    const int lane = tid & 31;
    const int g    = lane >> 2;
    const int tig  = lane & 3;
    const int warpM = wid >> 2;            // 0..1 -> 32 rows
    const int warpN = wid & 3;             // 0..3 -> 16 cols

    const float* Aptr = A + (size_t)by * 64 * K;

    float acc[2][2][4];
    #pragma unroll
    for (int ma = 0; ma < 2; ma++)
        #pragma unroll
        for (int na = 0; na < 2; na++)
            #pragma unroll
            for (int i = 0; i < 4; i++) acc[ma][na][i] = 0.f;

    for (int k0 = 0; k0 < K; k0 += 32) {
        #pragma unroll
        for (int i = 0; i < 2; i++) {
            int idx = tid + i * 256;
            int row = idx >> 3;
            int c4  = (idx & 7) * 4;
            float4 v = *(const float4*)(Aptr + (size_t)row * K + k0 + c4);
            *(float4*)&As[row * T2_APAD + c4] = v;
        }
        #pragma unroll
        for (int i = 0; i < 2; i++) {
            int idx = tid + i * 256;
            int krow = idx >> 4;
            int c4   = (idx & 15) * 4;
            const float* src = (c4 < 32)
                ? (Uw + (size_t)(k0 + krow) * 32 + c4)
                : (Vw + (size_t)(k0 + krow) * 32 + (c4 - 32));
            *(float4*)&Bs[krow * T2_BPAD + c4] = *(const float4*)src;
        }
        __syncthreads();

        #pragma unroll
        for (int ks = 0; ks < 4; ks++) {
            int kb = ks * 8;
            unsigned afr[2][4], bfr[2][2];
            #pragma unroll
            for (int ma = 0; ma < 2; ma++) {
                int r0 = warpM * 32 + ma * 16;
                afr[ma][0] = f2tf32(As[(r0 + g)     * T2_APAD + kb + tig]);
                afr[ma][1] = f2tf32(As[(r0 + g + 8) * T2_APAD + kb + tig]);
                afr[ma][2] = f2tf32(As[(r0 + g)     * T2_APAD + kb + tig + 4]);
                afr[ma][3] = f2tf32(As[(r0 + g + 8) * T2_APAD + kb + tig + 4]);
            }
            #pragma unroll
            for (int na = 0; na < 2; na++) {
                int c0 = warpN * 16 + na * 8;
                bfr[na][0] = f2tf32(Bs[(kb + tig)     * T2_BPAD + c0 + g]);
                bfr[na][1] = f2tf32(Bs[(kb + tig + 4) * T2_BPAD + c0 + g]);
            }
            #pragma unroll
            for (int ma = 0; ma < 2; ma++)
                #pragma unroll
                for (int na = 0; na < 2; na++)
                    mma_tf32(acc[ma][na], afr[ma], bfr[na]);
        }
        __syncthreads();
    }

    #pragma unroll
    for (int ma = 0; ma < 2; ma++) {
        int rbase = by * 64 + warpM * 32 + ma * 16;
        #pragma unroll
        for (int na = 0; na < 2; na++) {
            int col = warpN * 16 + na * 8 + tig * 2;
            float2 v;
            v.x = acc[ma][na][0]; v.y = acc[ma][na][1];
            *(float2*)&g_UV[(size_t)(rbase + g) * 64 + col] = v;
            v.x = acc[ma][na][2]; v.y = acc[ma][na][3];
            *(float2*)&g_UV[(size_t)(rbase + g + 8) * 64 + col] = v;
        }
    }
}

// ======================================================================
// K2b: gate = sigmoid(h @ W2 + b2); gateU = gate * U
// Block: 16 tokens x 32 cols, 256 threads; 2 tokens per thread.
// smem: hs 16 KB + w2s 32 KB = 48 KB (static limit).
// ======================================================================
__global__ void __launch_bounds__(256) k2b_gate(
    const float* __restrict__ W2,      // (256 x 32)
    const float* __restrict__ b2)      // (32)
{
    __shared__ float hs[16][GG];       // 16 KB
    __shared__ float w2s[GG * RR];     // 32 KB
    const int tid = threadIdx.x;
    const int tok0 = blockIdx.x * 16;

    const float4* src = (const float4*)(g_h + (size_t)tok0 * GG);
    #pragma unroll
    for (int i = 0; i < 4; i++)
        ((float4*)&hs[0][0])[tid + i * 256] = src[tid + i * 256];
    const float4* wsrc = (const float4*)W2;
    #pragma unroll
    for (int i = 0; i < 8; i++)
        ((float4*)w2s)[tid + i * 256] = wsrc[tid + i * 256];
    __syncthreads();

    const int grp = tid >> 5;          // 0..7
    const int c   = tid & 31;
    float bc = b2[c];
    float a0 = bc, a1 = bc;
    #pragma unroll 8
    for (int k = 0; k < GG; k++) {
        float w = w2s[k * 32 + c];
        a0 = fmaf(hs[grp][k],     w, a0);
        a1 = fmaf(hs[grp + 8][k], w, a1);
    }
    {
        int token = tok0 + grp;
        float gate = 1.f / (1.f + expf(-a0));
        g_gateU[(size_t)token * RR + c] = gate * g_UV[(size_t)token * 64 + c];
        token += 8;
        gate = 1.f / (1.f + expf(-a1));
        g_gateU[(size_t)token * RR + c] = gate * g_UV[(size_t)token * 64 + c];
    }
}

// ======================================================================
// K3a: segmented inclusive cumsum of V over L (NSEG=32 segments per batch).
// ======================================================================
__global__ void __launch_bounds__(1024) k3a_scan()
{
    const int b   = blockIdx.x >> 5;      // NSEG = 32
    const int seg = blockIdx.x & 31;
    __shared__ float buf[32][33];

    const int tid  = threadIdx.x;
    const int lane = tid & 31;
    const int warp = tid >> 5;
    const int l    = tid >> 5;
    const int r    = tid & 31;

    const float* Vb = g_UV + (size_t)(b * LL + seg * SEG) * 64 + 32;
    float*       Sb = g_glob + (size_t)(b * LL + seg * SEG) * RR;

    float carry = 0.f;
    for (int c = 0; c < SEG / 32; c++) {
        buf[l][r] = Vb[(size_t)(c * 32 + l) * 64 + r];
        __syncthreads();
        float v = buf[lane][warp];
        #pragma unroll
        for (int off = 1; off < 32; off <<= 1) {
            float n = __shfl_up_sync(0xffffffffu, v, off);
            if (lane >= off) v += n;
        }
        v += carry;
        carry = __shfl_sync(0xffffffffu, v, 31);
        buf[lane][warp] = v;
        __syncthreads();
        Sb[c * 1024 + tid] = buf[l][r];
        __syncthreads();
    }
    if (lane == 0)
        g_segsum[(b * NSEG + seg) * RR + warp] = carry;
}

// K3b: exclusive scan of segment totals (1 block, 128 threads = (b,r) pairs)
__global__ void k3b_segoff()
{
    int i = threadIdx.x;
    if (i < BB * RR) {
        int b = i >> 5, r = i & 31;
        float acc = 0.f;
        for (int s = 0; s < NSEG; s++) {
            g_segoff[(b * NSEG + s) * RR + r] = acc;
            acc += g_segsum[(b * NSEG + s) * RR + r];
        }
    }
}

// ======================================================================
// K4: out = (gateU*(S+off)) @ out_w + out_b + depthwise_conv3(x)
// TF32 mma: block = 128 tokens x 128 dcols, K=32 (single tile).
// k3c (glob finalize) fused into the A-tile build.
// 8 warps (2x4), warp tile 64x32 — same fragment layout as k1.
// ======================================================================
#define T4_APAD 36
#define T4_BPAD 136
__global__ void __launch_bounds__(256) k4_mma(
    const float* __restrict__ x,
    const float* __restrict__ conv_w,   // (1024 x 3)
    const float* __restrict__ out_w,    // (32 x 1024)
    const float* __restrict__ out_b,    // (1024)
    float* __restrict__ out)
{
    __shared__ unsigned Gs[128 * T4_APAD];  // glob tile (tokens x 32 ranks), tf32
    __shared__ unsigned Ws[32 * T4_BPAD];   // out_w tile (32 ranks x 128 cols), tf32

    const int tid  = threadIdx.x;
    const int bx   = blockIdx.x;            // d tile 0..7
    const int by   = blockIdx.y;            // token tile 0..127
    const int wid  = tid >> 5;
    const int lane = tid & 31;
    const int g    = lane >> 2;
    const int tig  = lane & 3;
    const int warpM = wid >> 2;             // 0..1
    const int warpN = wid & 3;              // 0..3

    const int token0 = by * 128;
    const int d0     = bx * 128;

    // ---- build glob tile: glob = gateU * (S_local + segoff), cvt to tf32 ----
    {
        const int b = token0 >> 12;                   // whole tile same batch
        #pragma unroll
        for (int i = 0; i < 16; i++) {
            int flat  = tid + i * 256;                // 0..4095
            int row   = flat >> 5;
            int r     = flat & 31;
            int token = token0 + row;
            int lpos  = token & (LL - 1);
            int seg   = lpos >> 7;                    // SEG = 128
            size_t gi = (size_t)token * RR + r;
            float S = g_glob[gi] + g_segoff[(b * NSEG + seg) * RR + r];
            Gs[row * T4_APAD + r] = f2tf32(g_gateU[gi] * S);
        }
        #pragma unroll
        for (int i = 0; i < 16; i++) {
            int flat = tid + i * 256;                 // 0..4095
            int r    = flat >> 7;                     // 0..31
            int c    = flat & 127;
            Ws[r * T4_BPAD + c] = f2tf32(__ldg(out_w + (size_t)r * DD + d0 + c));
        }
    }
    __syncthreads();

    // ---- mma: 4 k8 steps over K=32 ----
    float acc[4][4][4];
    #pragma unroll
    for (int ma = 0; ma < 4; ma++)
        #pragma unroll
        for (int na = 0; na < 4; na++)
            #pragma unroll
            for (int i = 0; i < 4; i++) acc[ma][na][i] = 0.f;

    #pragma unroll
    for (int ks = 0; ks < 4; ks++) {
        int kb = ks * 8;
        unsigned afr[4][4], bfr[4][2];
        #pragma unroll
        for (int ma = 0; ma < 4; ma++) {
            int r0 = warpM * 64 + ma * 16;
            afr[ma][0] = Gs[(r0 + g)     * T4_APAD + kb + tig];
            afr[ma][1] = Gs[(r0 + g + 8) * T4_APAD + kb + tig];
            afr[ma][2] = Gs[(r0 + g)     * T4_APAD + kb + tig + 4];
            afr[ma][3] = Gs[(r0 + g + 8) * T4_APAD + kb + tig + 4];
        }
        #pragma unroll
        for (int na = 0; na < 4; na++) {
            int c0 = warpN * 32 + na * 8;
            bfr[na][0] = Ws[(kb + tig)     * T4_BPAD + c0 + g];
            bfr[na][1] = Ws[(kb + tig + 4) * T4_BPAD + c0 + g];
        }
        #pragma unroll
        for (int ma = 0; ma < 4; ma++)
            #pragma unroll
            for (int na = 0; na < 4; na++)
                mma_tf32(acc[ma][na], afr[ma], bfr[na]);
    }

    // ---- epilogue: + out_b + depthwise conv3(x), write out ----
    float cwm[4][2], cwc[4][2], cwp[4][2], bb[4][2];
    #pragma unroll
    for (int na = 0; na < 4; na++) {
        int c = d0 + warpN * 32 + na * 8 + tig * 2;
        cwm[na][0] = __ldg(conv_w + c * 3 + 0);
        cwc[na][0] = __ldg(conv_w + c * 3 + 1);
        cwp[na][0] = __ldg(conv_w + c * 3 + 2);
        cwm[na][1] = __ldg(conv_w + (c + 1) * 3 + 0);
        cwc[na][1] = __ldg(conv_w + (c + 1) * 3 + 1);
        cwp[na][1] = __ldg(conv_w + (c + 1) * 3 + 2);
        bb[na][0]  = __ldg(out_b + c);
        bb[na][1]  = __ldg(out_b + c + 1);
    }

    #pragma unroll
    for (int ma = 0; ma < 4; ma++) {
        #pragma unroll
        for (int rh = 0; rh < 2; rh++) {            // row half: g / g+8
            int token = token0 + warpM * 64 + ma * 16 + g + rh * 8;
            int lpos  = token & (LL - 1);
            #pragma unroll
            for (int na = 0; na < 4; na++) {
                int c = d0 + warpN * 32 + na * 8 + tig * 2;
                const float* xr = x + (size_t)token * DD + c;
                float2 xc = *(const float2*)xr;
                float2 xm = (lpos > 0)      ? *(const float2*)(xr - DD) : make_float2(0.f, 0.f);
                float2 xp = (lpos < LL - 1) ? *(const float2*)(xr + DD) : make_float2(0.f, 0.f);
                float a0 = acc[ma][na][rh * 2 + 0];
                float a1 = acc[ma][na][rh * 2 + 1];
                float2 o;
                o.x = a0 + bb[na][0] + cwm[na][0] * xm.x + cwc[na][0] * xc.x + cwp[na][0] * xp.x;
                o.y = a1 + bb[na][1] + cwm[na][1] * xm.y + cwc[na][1] * xc.y + cwp[na][1] * xp.y;
                *(float2*)(out + (size_t)token * DD + c) = o;
            }
        }
    }
}

// ======================================================================
extern "C" void kernel_launch(void* const* d_in, const int* in_sizes, int n_in,
                              void* d_out, int out_size)
{
    const float* x       = (const float*)d_in[0];
    const float* gate_w1 = (const float*)d_in[1];
    const float* gate_b1 = (const float*)d_in[2];
    const float* gate_w2 = (const float*)d_in[3];
    const float* gate_b2 = (const float*)d_in[4];
    const float* U_w     = (const float*)d_in[5];
    const float* V_w     = (const float*)d_in[6];
    const float* conv_w  = (const float*)d_in[7];
    const float* out_w   = (const float*)d_in[8];
    const float* out_b   = (const float*)d_in[9];
    float* out = (float*)d_out;

    // K1: h = relu(x@W1+b1)  (tf32 tensor cores)
    k1_tf32<<<dim3(GG / 128, MTOK / 128), 256>>>(x, gate_w1, gate_b1);
    // K2a: UV = x@[Uw|Vw]    (tf32 tensor cores)
    k2a_tf32<<<MTOK / 64, 256>>>(x, U_w, V_w);
    // K2b: gateU
    k2b_gate<<<MTOK / 16, 256>>>(gate_w2, gate_b2);
    // K3: segmented cumsum of V
    k3a_scan<<<BB * NSEG, 1024>>>();
    k3b_segoff<<<1, 128>>>();
    // K4: out = glob@out_w + bias + conv  (tf32 mma, k3c fused)
    k4_mma<<<dim3(DD / 128, MTOK / 128), 256>>>(x, conv_w, out_w, out_b, out);
}

// round 7
// speedup vs baseline: 2.6588x; 1.0294x over previous
#include <cuda_runtime.h>
#include <cuda_bf16.h>
#include <math.h>

// Problem constants
#define BB 4
#define LL 4096
#define DD 1024
#define RR 32
#define GG 256
#define MTOK (BB*LL)          // 16384 tokens
#define NSEG 32
#define SEG  (LL/NSEG)        // 128

// ---------------- scratch (static device memory; no allocations) ----------------
__device__ float g_h[MTOK * GG];        // 16 MB : relu(x@W1+b1)
__device__ float g_UV[MTOK * 64];       //  4 MB : cols 0..31 = U, 32..63 = V
__device__ float g_gateU[MTOK * RR];    //  2 MB : sigmoid(h@W2+b2) * U
__device__ float g_glob[MTOK * RR];     //  2 MB : local (per-segment) cumsum of V
__device__ float g_segsum[BB * NSEG * RR];

// ---------------- tf32 helpers ----------------
__device__ __forceinline__ unsigned f2tf32(float f) {
    unsigned r;
    asm("cvt.rna.tf32.f32 %0, %1;" : "=r"(r) : "f"(f));
    return r;
}

__device__ __forceinline__ void mma_tf32(float* d, const unsigned* a, const unsigned* b) {
    asm volatile(
        "mma.sync.aligned.m16n8k8.row.col.f32.tf32.tf32.f32 "
        "{%0,%1,%2,%3}, {%4,%5,%6,%7}, {%8,%9}, {%0,%1,%2,%3};"
        : "+f"(d[0]), "+f"(d[1]), "+f"(d[2]), "+f"(d[3])
        : "r"(a[0]), "r"(a[1]), "r"(a[2]), "r"(a[3]), "r"(b[0]), "r"(b[1]));
}

// ======================================================================
// K12 (fused K1+K2a): one pass over x computes
//   bx=0:  h[:,0:128]   and U = x@Uw
//   bx=1:  h[:,128:256] and V = x@Vw
// Block 128(M) x 160(N) x 32(K).  8 warps (2x4), warp tile 64x40 (4x5 atoms).
// tf32 stored in smem (cvt once); register prefetch of next k-tile.
// ======================================================================
#define F_APAD 36
#define F_BPAD 168
__global__ void __launch_bounds__(256) k12_tf32(
    const float* __restrict__ A,      // x       (M x 1024)
    const float* __restrict__ W,      // gate_w1 (1024 x 256)
    const float* __restrict__ bias,   // gate_b1 (256)
    const float* __restrict__ Uw,     // (1024 x 32)
    const float* __restrict__ Vw)     // (1024 x 32)
{
    const int K = DD;
    __shared__ unsigned As[128 * F_APAD];   // 18.4 KB
    __shared__ unsigned Bs[32 * F_BPAD];    // 21.5 KB

    const int tid  = threadIdx.x;
    const int bx   = blockIdx.x;           // 0..1 (h half + U/V select)
    const int by   = blockIdx.y;           // M tile 0..127
    const int wid  = tid >> 5;
    const int lane = tid & 31;
    const int g    = lane >> 2;            // 0..7
    const int tig  = lane & 3;             // 0..3
    const int warpM = wid >> 2;            // 0..1 -> 64 rows
    const int warpN = wid & 3;             // 0..3 -> 40 cols

    const float* Aptr  = A + (size_t)by * 128 * K;
    const float* Wptr  = W + bx * 128;
    const float* UVptr = bx ? Vw : Uw;

    // per-thread load coordinates
    const int aRow = tid >> 3;             // 0..31 (x4 -> 128 rows)
    const int aC4  = (tid & 7) * 4;

    float acc[4][5][4];
    #pragma unroll
    for (int ma = 0; ma < 4; ma++)
        #pragma unroll
        for (int na = 0; na < 5; na++)
            #pragma unroll
            for (int i = 0; i < 4; i++) acc[ma][na][i] = 0.f;

    float4 pa[4], pb[5];
    // prologue loads (k0 = 0)
    #pragma unroll
    for (int i = 0; i < 4; i++)
        pa[i] = *(const float4*)(Aptr + (size_t)(aRow + i * 32) * K + aC4);
    #pragma unroll
    for (int i = 0; i < 5; i++) {
        int idx  = tid + i * 256;          // 0..1279
        int krow = idx / 40;
        int c4   = (idx % 40) * 4;         // 0..156
        pb[i] = (c4 < 128)
            ? *(const float4*)(Wptr + (size_t)krow * GG + c4)
            : *(const float4*)(UVptr + (size_t)krow * 32 + (c4 - 128));
    }

    for (int k0 = 0; k0 < K; k0 += 32) {
        // store current tile with cvt
        #pragma unroll
        for (int i = 0; i < 4; i++) {
            int row = aRow + i * 32;
            As[row * F_APAD + aC4 + 0] = f2tf32(pa[i].x);
            As[row * F_APAD + aC4 + 1] = f2tf32(pa[i].y);
            As[row * F_APAD + aC4 + 2] = f2tf32(pa[i].z);
            As[row * F_APAD + aC4 + 3] = f2tf32(pa[i].w);
        }
        #pragma unroll
        for (int i = 0; i < 5; i++) {
            int idx  = tid + i * 256;
            int krow = idx / 40;
            int c4   = (idx % 40) * 4;
            Bs[krow * F_BPAD + c4 + 0] = f2tf32(pb[i].x);
            Bs[krow * F_BPAD + c4 + 1] = f2tf32(pb[i].y);
            Bs[krow * F_BPAD + c4 + 2] = f2tf32(pb[i].z);
            Bs[krow * F_BPAD + c4 + 3] = f2tf32(pb[i].w);
        }
        __syncthreads();

        // prefetch next k-tile (overlaps with mma below)
        if (k0 + 32 < K) {
            #pragma unroll
            for (int i = 0; i < 4; i++)
                pa[i] = *(const float4*)(Aptr + (size_t)(aRow + i * 32) * K + (k0 + 32) + aC4);
            #pragma unroll
            for (int i = 0; i < 5; i++) {
                int idx  = tid + i * 256;
                int krow = k0 + 32 + idx / 40;
                int c4   = (idx % 40) * 4;
                pb[i] = (c4 < 128)
                    ? *(const float4*)(Wptr + (size_t)krow * GG + c4)
                    : *(const float4*)(UVptr + (size_t)krow * 32 + (c4 - 128));
            }
        }

        #pragma unroll
        for (int ks = 0; ks < 4; ks++) {
            int kb = ks * 8;
            unsigned afr[4][4], bfr[5][2];
            #pragma unroll
            for (int ma = 0; ma < 4; ma++) {
                int r0 = warpM * 64 + ma * 16;
                afr[ma][0] = As[(r0 + g)     * F_APAD + kb + tig];
                afr[ma][1] = As[(r0 + g + 8) * F_APAD + kb + tig];
                afr[ma][2] = As[(r0 + g)     * F_APAD + kb + tig + 4];
                afr[ma][3] = As[(r0 + g + 8) * F_APAD + kb + tig + 4];
            }
            #pragma unroll
            for (int na = 0; na < 5; na++) {
                int c0 = warpN * 40 + na * 8;
                bfr[na][0] = Bs[(kb + tig)     * F_BPAD + c0 + g];
                bfr[na][1] = Bs[(kb + tig + 4) * F_BPAD + c0 + g];
            }
            #pragma unroll
            for (int ma = 0; ma < 4; ma++)
                #pragma unroll
                for (int na = 0; na < 5; na++)
                    mma_tf32(acc[ma][na], afr[ma], bfr[na]);
        }
        __syncthreads();
    }

    // epilogue: cols <128 -> bias+relu -> g_h ; cols >=128 -> raw -> g_UV
    #pragma unroll
    for (int ma = 0; ma < 4; ma++) {
        int rbase = by * 128 + warpM * 64 + ma * 16;
        #pragma unroll
        for (int na = 0; na < 5; na++) {
            int colBlk = warpN * 40 + na * 8 + tig * 2;   // 0..158
            if (colBlk < 128) {
                int col = bx * 128 + colBlk;
                float b0 = __ldg(bias + col), b1 = __ldg(bias + col + 1);
                float2 v;
                v.x = fmaxf(acc[ma][na][0] + b0, 0.f);
                v.y = fmaxf(acc[ma][na][1] + b1, 0.f);
                *(float2*)&g_h[(size_t)(rbase + g) * GG + col] = v;
                v.x = fmaxf(acc[ma][na][2] + b0, 0.f);
                v.y = fmaxf(acc[ma][na][3] + b1, 0.f);
                *(float2*)&g_h[(size_t)(rbase + g + 8) * GG + col] = v;
            } else {
                int col = bx * 32 + (colBlk - 128);       // U at 0..31, V at 32..63
                float2 v;
                v.x = acc[ma][na][0]; v.y = acc[ma][na][1];
                *(float2*)&g_UV[(size_t)(rbase + g) * 64 + col] = v;
                v.x = acc[ma][na][2]; v.y = acc[ma][na][3];
                *(float2*)&g_UV[(size_t)(rbase + g + 8) * 64 + col] = v;
            }
        }
    }
}

// ======================================================================
// K2b: gate = sigmoid(h @ W2 + b2); gateU = gate * U
// Block: 16 tokens x 32 cols, 256 threads; 2 tokens per thread.
// smem: hs 16 KB + w2s 32 KB = 48 KB (static limit).
// ======================================================================
__global__ void __launch_bounds__(256) k2b_gate(
    const float* __restrict__ W2,      // (256 x 32)
    const float* __restrict__ b2)      // (32)
{
    __shared__ float hs[16][GG];       // 16 KB
    __shared__ float w2s[GG * RR];     // 32 KB
    const int tid = threadIdx.x;
    const int tok0 = blockIdx.x * 16;

    const float4* src = (const float4*)(g_h + (size_t)tok0 * GG);
    #pragma unroll
    for (int i = 0; i < 4; i++)
        ((float4*)&hs[0][0])[tid + i * 256] = src[tid + i * 256];
    const float4* wsrc = (const float4*)W2;
    #pragma unroll
    for (int i = 0; i < 8; i++)
        ((float4*)w2s)[tid + i * 256] = wsrc[tid + i * 256];
    __syncthreads();

    const int grp = tid >> 5;          // 0..7
    const int c   = tid & 31;
    float bc = b2[c];
    float a0 = bc, a1 = bc;
    #pragma unroll 8
    for (int k = 0; k < GG; k++) {
        float w = w2s[k * 32 + c];
        a0 = fmaf(hs[grp][k],     w, a0);
        a1 = fmaf(hs[grp + 8][k], w, a1);
    }
    {
        int token = tok0 + grp;
        float gate = 1.f / (1.f + expf(-a0));
        g_gateU[(size_t)token * RR + c] = gate * g_UV[(size_t)token * 64 + c];
        token += 8;
        gate = 1.f / (1.f + expf(-a1));
        g_gateU[(size_t)token * RR + c] = gate * g_UV[(size_t)token * 64 + c];
    }
}

// ======================================================================
// K3a: segmented inclusive cumsum of V over L (NSEG=32 segments per batch).
// Writes local cumsum to g_glob and per-segment totals to g_segsum.
// ======================================================================
__global__ void __launch_bounds__(1024) k3a_scan()
{
    const int b   = blockIdx.x >> 5;      // NSEG = 32
    const int seg = blockIdx.x & 31;
    __shared__ float buf[32][33];

    const int tid  = threadIdx.x;
    const int lane = tid & 31;
    const int warp = tid >> 5;
    const int l    = tid >> 5;
    const int r    = tid & 31;

    const float* Vb = g_UV + (size_t)(b * LL + seg * SEG) * 64 + 32;
    float*       Sb = g_glob + (size_t)(b * LL + seg * SEG) * RR;

    float carry = 0.f;
    for (int c = 0; c < SEG / 32; c++) {
        buf[l][r] = Vb[(size_t)(c * 32 + l) * 64 + r];
        __syncthreads();
        float v = buf[lane][warp];
        #pragma unroll
        for (int off = 1; off < 32; off <<= 1) {
            float n = __shfl_up_sync(0xffffffffu, v, off);
            if (lane >= off) v += n;
        }
        v += carry;
        carry = __shfl_sync(0xffffffffu, v, 31);
        buf[lane][warp] = v;
        __syncthreads();
        Sb[c * 1024 + tid] = buf[l][r];
        __syncthreads();
    }
    if (lane == 0)
        g_segsum[(b * NSEG + seg) * RR + warp] = carry;
}

// ======================================================================
// K4: out = (gateU*(S+off)) @ out_w + out_b + depthwise_conv3(x)
// TF32 mma: block = 128 tokens x 128 dcols, K=32 (single tile).
// Each 128-token tile lies in EXACTLY one segment -> segment offset
// computed inline from g_segsum (k3b launch eliminated).
// ======================================================================
#define T4_APAD 36
#define T4_BPAD 136
__global__ void __launch_bounds__(256) k4_mma(
    const float* __restrict__ x,
    const float* __restrict__ conv_w,   // (1024 x 3)
    const float* __restrict__ out_w,    // (32 x 1024)
    const float* __restrict__ out_b,    // (1024)
    float* __restrict__ out)
{
    __shared__ unsigned Gs[128 * T4_APAD];  // glob tile (tokens x 32 ranks), tf32
    __shared__ unsigned Ws[32 * T4_BPAD];   // out_w tile (32 ranks x 128 cols), tf32

    const int tid  = threadIdx.x;
    const int bx   = blockIdx.x;            // d tile 0..7
    const int by   = blockIdx.y;            // token tile 0..127
    const int wid  = tid >> 5;
    const int lane = tid & 31;
    const int g    = lane >> 2;
    const int tig  = lane & 3;
    const int warpM = wid >> 2;             // 0..1
    const int warpN = wid & 3;              // 0..3

    const int token0 = by * 128;
    const int d0     = bx * 128;

    // ---- inline segment offset for this tile's single (b, seg) ----
    // Each thread's Gs entries all share rank r = tid & 31.
    const int b   = token0 >> 12;
    const int seg = (token0 & (LL - 1)) >> 7;     // SEG = 128
    const int r   = tid & 31;
    float soff = 0.f;
    for (int s = 0; s < seg; s++)
        soff += g_segsum[(b * NSEG + s) * RR + r];

    // ---- build glob tile: glob = gateU * (S_local + soff), cvt to tf32 ----
    #pragma unroll
    for (int i = 0; i < 16; i++) {
        int flat  = tid + i * 256;                // 0..4095 ; rank = tid&31 = r
        int row   = flat >> 5;
        size_t gi = (size_t)(token0 + row) * RR + r;
        float S = g_glob[gi] + soff;
        Gs[row * T4_APAD + r] = f2tf32(g_gateU[gi] * S);
    }
    #pragma unroll
    for (int i = 0; i < 16; i++) {
        int flat = tid + i * 256;                 // 0..4095
        int rr   = flat >> 7;                     // 0..31
        int c    = flat & 127;
        Ws[rr * T4_BPAD + c] = f2tf32(__ldg(out_w + (size_t)rr * DD + d0 + c));
    }
    __syncthreads();

    // ---- mma: 4 k8 steps over K=32 ----
    float acc[4][4][4];
    #pragma unroll
    for (int ma = 0; ma < 4; ma++)
        #pragma unroll
        for (int na = 0; na < 4; na++)
            #pragma unroll
            for (int i = 0; i < 4; i++) acc[ma][na][i] = 0.f;

    #pragma unroll
    for (int ks = 0; ks < 4; ks++) {
        int kb = ks * 8;
        unsigned afr[4][4], bfr[4][2];
        #pragma unroll
        for (int ma = 0; ma < 4; ma++) {
            int r0 = warpM * 64 + ma * 16;
            afr[ma][0] = Gs[(r0 + g)     * T4_APAD + kb + tig];
            afr[ma][1] = Gs[(r0 + g + 8) * T4_APAD + kb + tig];
            afr[ma][2] = Gs[(r0 + g)     * T4_APAD + kb + tig + 4];
            afr[ma][3] = Gs[(r0 + g + 8) * T4_APAD + kb + tig + 4];
        }
        #pragma unroll
        for (int na = 0; na < 4; na++) {
            int c0 = warpN * 32 + na * 8;
            bfr[na][0] = Ws[(kb + tig)     * T4_BPAD + c0 + g];
            bfr[na][1] = Ws[(kb + tig + 4) * T4_BPAD + c0 + g];
        }
        #pragma unroll
        for (int ma = 0; ma < 4; ma++)
            #pragma unroll
            for (int na = 0; na < 4; na++)
                mma_tf32(acc[ma][na], afr[ma], bfr[na]);
    }

    // ---- epilogue: + out_b + depthwise conv3(x), write out ----
    float cwm[4][2], cwc[4][2], cwp[4][2], bb4[4][2];
    #pragma unroll
    for (int na = 0; na < 4; na++) {
        int c = d0 + warpN * 32 + na * 8 + tig * 2;
        cwm[na][0] = __ldg(conv_w + c * 3 + 0);
        cwc[na][0] = __ldg(conv_w + c * 3 + 1);
        cwp[na][0] = __ldg(conv_w + c * 3 + 2);
        cwm[na][1] = __ldg(conv_w + (c + 1) * 3 + 0);
        cwc[na][1] = __ldg(conv_w + (c + 1) * 3 + 1);
        cwp[na][1] = __ldg(conv_w + (c + 1) * 3 + 2);
        bb4[na][0] = __ldg(out_b + c);
        bb4[na][1] = __ldg(out_b + c + 1);
    }

    #pragma unroll
    for (int ma = 0; ma < 4; ma++) {
        #pragma unroll
        for (int rh = 0; rh < 2; rh++) {            // row half: g / g+8
            int token = token0 + warpM * 64 + ma * 16 + g + rh * 8;
            int lpos  = token & (LL - 1);
            #pragma unroll
            for (int na = 0; na < 4; na++) {
                int c = d0 + warpN * 32 + na * 8 + tig * 2;
                const float* xr = x + (size_t)token * DD + c;
                float2 xc = *(const float2*)xr;
                float2 xm = (lpos > 0)      ? *(const float2*)(xr - DD) : make_float2(0.f, 0.f);
                float2 xp = (lpos < LL - 1) ? *(const float2*)(xr + DD) : make_float2(0.f, 0.f);
                float a0 = acc[ma][na][rh * 2 + 0];
                float a1 = acc[ma][na][rh * 2 + 1];
                float2 o;
                o.x = a0 + bb4[na][0] + cwm[na][0] * xm.x + cwc[na][0] * xc.x + cwp[na][0] * xp.x;
                o.y = a1 + bb4[na][1] + cwm[na][1] * xm.y + cwc[na][1] * xc.y + cwp[na][1] * xp.y;
                *(float2*)(out + (size_t)token * DD + c) = o;
            }
        }
    }
}

// ======================================================================
extern "C" void kernel_launch(void* const* d_in, const int* in_sizes, int n_in,
                              void* d_out, int out_size)
{
    const float* x       = (const float*)d_in[0];
    const float* gate_w1 = (const float*)d_in[1];
    const float* gate_b1 = (const float*)d_in[2];
    const float* gate_w2 = (const float*)d_in[3];
    const float* gate_b2 = (const float*)d_in[4];
    const float* U_w     = (const float*)d_in[5];
    const float* V_w     = (const float*)d_in[6];
    const float* conv_w  = (const float*)d_in[7];
    const float* out_w   = (const float*)d_in[8];
    const float* out_b   = (const float*)d_in[9];
    float* out = (float*)d_out;

    // K12: h = relu(x@W1+b1) AND UV = x@[Uw|Vw]  (single pass over x)
    k12_tf32<<<dim3(2, MTOK / 128), 256>>>(x, gate_w1, gate_b1, U_w, V_w);
    // K2b: gateU
    k2b_gate<<<MTOK / 16, 256>>>(gate_w2, gate_b2);
    // K3a: segmented cumsum of V (totals to g_segsum)
    k3a_scan<<<BB * NSEG, 1024>>>();
    // K4: out = glob@out_w + bias + conv  (tf32 mma; k3c+k3b fused)
    k4_mma<<<dim3(DD / 128, MTOK / 128), 256>>>(x, conv_w, out_w, out_b, out);
}

// round 8
// speedup vs baseline: 2.8218x; 1.0613x over previous
#include <cuda_runtime.h>
#include <cuda_bf16.h>
#include <math.h>

// Problem constants
#define BB 4
#define LL 4096
#define DD 1024
#define RR 32
#define GG 256
#define MTOK (BB*LL)          // 16384 tokens
#define NSEG 32
#define SEG  (LL/NSEG)        // 128

// ---------------- scratch (static device memory; no allocations) ----------------
__device__ float g_h[MTOK * GG];        // 16 MB : relu(x@W1+b1)
__device__ float g_UV[MTOK * 64];       //  4 MB : cols 0..31 = U, 32..63 = V
__device__ float g_gateU[MTOK * RR];    //  2 MB : sigmoid(h@W2+b2) * U
__device__ float g_glob[MTOK * RR];     //  2 MB : local (per-segment) cumsum of V
__device__ float g_segsum[BB * NSEG * RR];

// ---------------- tf32 helpers ----------------
__device__ __forceinline__ unsigned f2tf32(float f) {
    unsigned r;
    asm("cvt.rna.tf32.f32 %0, %1;" : "=r"(r) : "f"(f));
    return r;
}

__device__ __forceinline__ void mma_tf32(float* d, const unsigned* a, const unsigned* b) {
    asm volatile(
        "mma.sync.aligned.m16n8k8.row.col.f32.tf32.tf32.f32 "
        "{%0,%1,%2,%3}, {%4,%5,%6,%7}, {%8,%9}, {%0,%1,%2,%3};"
        : "+f"(d[0]), "+f"(d[1]), "+f"(d[2]), "+f"(d[3])
        : "r"(a[0]), "r"(a[1]), "r"(a[2]), "r"(a[3]), "r"(b[0]), "r"(b[1]));
}

// ======================================================================
// K12 (fused K1+K2a): one pass over x computes
//   bx=0:  h[:,0:128]   and U = x@Uw
//   bx=1:  h[:,128:256] and V = x@Vw
// Block 64(M) x 160(N) x 32(K).  8 warps (2x4), warp tile 32x40 (2x5 atoms).
// 2 CTAs/SM (reg-capped at 128); register prefetch of next k-tile.
// ======================================================================
#define F_APAD 36
#define F_BPAD 168
__global__ void __launch_bounds__(256, 2) k12_tf32(
    const float* __restrict__ A,      // x       (M x 1024)
    const float* __restrict__ W,      // gate_w1 (1024 x 256)
    const float* __restrict__ bias,   // gate_b1 (256)
    const float* __restrict__ Uw,     // (1024 x 32)
    const float* __restrict__ Vw)     // (1024 x 32)
{
    const int K = DD;
    __shared__ unsigned As[64 * F_APAD];    // 9.2 KB
    __shared__ unsigned Bs[32 * F_BPAD];    // 21.5 KB

    const int tid  = threadIdx.x;
    const int bx   = blockIdx.x;           // 0..1 (h half + U/V select)
    const int by   = blockIdx.y;           // M tile 0..255
    const int wid  = tid >> 5;
    const int lane = tid & 31;
    const int g    = lane >> 2;            // 0..7
    const int tig  = lane & 3;             // 0..3
    const int warpM = wid >> 2;            // 0..1 -> 32 rows
    const int warpN = wid & 3;             // 0..3 -> 40 cols

    const float* Aptr  = A + (size_t)by * 64 * K;
    const float* Wptr  = W + bx * 128;
    const float* UVptr = bx ? Vw : Uw;

    // per-thread load coordinates
    const int aRow = tid >> 3;             // 0..31 (x2 -> 64 rows)
    const int aC4  = (tid & 7) * 4;

    float acc[2][5][4];
    #pragma unroll
    for (int ma = 0; ma < 2; ma++)
        #pragma unroll
        for (int na = 0; na < 5; na++)
            #pragma unroll
            for (int i = 0; i < 4; i++) acc[ma][na][i] = 0.f;

    float4 pa[2], pb[5];
    // prologue loads (k0 = 0)
    #pragma unroll
    for (int i = 0; i < 2; i++)
        pa[i] = *(const float4*)(Aptr + (size_t)(aRow + i * 32) * K + aC4);
    #pragma unroll
    for (int i = 0; i < 5; i++) {
        int idx  = tid + i * 256;          // 0..1279
        int krow = idx / 40;
        int c4   = (idx % 40) * 4;         // 0..156
        pb[i] = (c4 < 128)
            ? *(const float4*)(Wptr + (size_t)krow * GG + c4)
            : *(const float4*)(UVptr + (size_t)krow * 32 + (c4 - 128));
    }

    for (int k0 = 0; k0 < K; k0 += 32) {
        // store current tile with cvt
        #pragma unroll
        for (int i = 0; i < 2; i++) {
            int row = aRow + i * 32;
            As[row * F_APAD + aC4 + 0] = f2tf32(pa[i].x);
            As[row * F_APAD + aC4 + 1] = f2tf32(pa[i].y);
            As[row * F_APAD + aC4 + 2] = f2tf32(pa[i].z);
            As[row * F_APAD + aC4 + 3] = f2tf32(pa[i].w);
        }
        #pragma unroll
        for (int i = 0; i < 5; i++) {
            int idx  = tid + i * 256;
            int krow = idx / 40;
            int c4   = (idx % 40) * 4;
            Bs[krow * F_BPAD + c4 + 0] = f2tf32(pb[i].x);
            Bs[krow * F_BPAD + c4 + 1] = f2tf32(pb[i].y);
            Bs[krow * F_BPAD + c4 + 2] = f2tf32(pb[i].z);
            Bs[krow * F_BPAD + c4 + 3] = f2tf32(pb[i].w);
        }
        __syncthreads();

        // prefetch next k-tile (overlaps with mma below)
        if (k0 + 32 < K) {
            #pragma unroll
            for (int i = 0; i < 2; i++)
                pa[i] = *(const float4*)(Aptr + (size_t)(aRow + i * 32) * K + (k0 + 32) + aC4);
            #pragma unroll
            for (int i = 0; i < 5; i++) {
                int idx  = tid + i * 256;
                int krow = k0 + 32 + idx / 40;
                int c4   = (idx % 40) * 4;
                pb[i] = (c4 < 128)
                    ? *(const float4*)(Wptr + (size_t)krow * GG + c4)
                    : *(const float4*)(UVptr + (size_t)krow * 32 + (c4 - 128));
            }
        }

        #pragma unroll
        for (int ks = 0; ks < 4; ks++) {
            int kb = ks * 8;
            unsigned afr[2][4], bfr[5][2];
            #pragma unroll
            for (int ma = 0; ma < 2; ma++) {
                int r0 = warpM * 32 + ma * 16;
                afr[ma][0] = As[(r0 + g)     * F_APAD + kb + tig];
                afr[ma][1] = As[(r0 + g + 8) * F_APAD + kb + tig];
                afr[ma][2] = As[(r0 + g)     * F_APAD + kb + tig + 4];
                afr[ma][3] = As[(r0 + g + 8) * F_APAD + kb + tig + 4];
            }
            #pragma unroll
            for (int na = 0; na < 5; na++) {
                int c0 = warpN * 40 + na * 8;
                bfr[na][0] = Bs[(kb + tig)     * F_BPAD + c0 + g];
                bfr[na][1] = Bs[(kb + tig + 4) * F_BPAD + c0 + g];
            }
            #pragma unroll
            for (int ma = 0; ma < 2; ma++)
                #pragma unroll
                for (int na = 0; na < 5; na++)
                    mma_tf32(acc[ma][na], afr[ma], bfr[na]);
        }
        __syncthreads();
    }

    // epilogue: cols <128 -> bias+relu -> g_h ; cols >=128 -> raw -> g_UV
    #pragma unroll
    for (int ma = 0; ma < 2; ma++) {
        int rbase = by * 64 + warpM * 32 + ma * 16;
        #pragma unroll
        for (int na = 0; na < 5; na++) {
            int colBlk = warpN * 40 + na * 8 + tig * 2;   // 0..158
            if (colBlk < 128) {
                int col = bx * 128 + colBlk;
                float b0 = __ldg(bias + col), b1 = __ldg(bias + col + 1);
                float2 v;
                v.x = fmaxf(acc[ma][na][0] + b0, 0.f);
                v.y = fmaxf(acc[ma][na][1] + b1, 0.f);
                *(float2*)&g_h[(size_t)(rbase + g) * GG + col] = v;
                v.x = fmaxf(acc[ma][na][2] + b0, 0.f);
                v.y = fmaxf(acc[ma][na][3] + b1, 0.f);
                *(float2*)&g_h[(size_t)(rbase + g + 8) * GG + col] = v;
            } else {
                int col = bx * 32 + (colBlk - 128);       // U at 0..31, V at 32..63
                float2 v;
                v.x = acc[ma][na][0]; v.y = acc[ma][na][1];
                *(float2*)&g_UV[(size_t)(rbase + g) * 64 + col] = v;
                v.x = acc[ma][na][2]; v.y = acc[ma][na][3];
                *(float2*)&g_UV[(size_t)(rbase + g + 8) * 64 + col] = v;
            }
        }
    }
}

// ======================================================================
// K2b: gate = sigmoid(h @ W2 + b2); gateU = gate * U
// Block: 16 tokens x 32 cols, 256 threads; 2 tokens per thread.
// smem: hs 16 KB + w2s 32 KB = 48 KB (static limit).
// ======================================================================
__global__ void __launch_bounds__(256) k2b_gate(
    const float* __restrict__ W2,      // (256 x 32)
    const float* __restrict__ b2)      // (32)
{
    __shared__ float hs[16][GG];       // 16 KB
    __shared__ float w2s[GG * RR];     // 32 KB
    const int tid = threadIdx.x;
    const int tok0 = blockIdx.x * 16;

    const float4* src = (const float4*)(g_h + (size_t)tok0 * GG);
    #pragma unroll
    for (int i = 0; i < 4; i++)
        ((float4*)&hs[0][0])[tid + i * 256] = src[tid + i * 256];
    const float4* wsrc = (const float4*)W2;
    #pragma unroll
    for (int i = 0; i < 8; i++)
        ((float4*)w2s)[tid + i * 256] = wsrc[tid + i * 256];
    __syncthreads();

    const int grp = tid >> 5;          // 0..7
    const int c   = tid & 31;
    float bc = b2[c];
    float a0 = bc, a1 = bc;
    #pragma unroll 8
    for (int k = 0; k < GG; k++) {
        float w = w2s[k * 32 + c];
        a0 = fmaf(hs[grp][k],     w, a0);
        a1 = fmaf(hs[grp + 8][k], w, a1);
    }
    {
        int token = tok0 + grp;
        float gate = 1.f / (1.f + expf(-a0));
        g_gateU[(size_t)token * RR + c] = gate * g_UV[(size_t)token * 64 + c];
        token += 8;
        gate = 1.f / (1.f + expf(-a1));
        g_gateU[(size_t)token * RR + c] = gate * g_UV[(size_t)token * 64 + c];
    }
}

// ======================================================================
// K3a: segmented inclusive cumsum of V over L (NSEG=32 segments per batch).
// Writes local cumsum to g_glob and per-segment totals to g_segsum.
// ======================================================================
__global__ void __launch_bounds__(1024) k3a_scan()
{
    const int b   = blockIdx.x >> 5;      // NSEG = 32
    const int seg = blockIdx.x & 31;
    __shared__ float buf[32][33];

    const int tid  = threadIdx.x;
    const int lane = tid & 31;
    const int warp = tid >> 5;
    const int l    = tid >> 5;
    const int r    = tid & 31;

    const float* Vb = g_UV + (size_t)(b * LL + seg * SEG) * 64 + 32;
    float*       Sb = g_glob + (size_t)(b * LL + seg * SEG) * RR;

    float carry = 0.f;
    for (int c = 0; c < SEG / 32; c++) {
        buf[l][r] = Vb[(size_t)(c * 32 + l) * 64 + r];
        __syncthreads();
        float v = buf[lane][warp];
        #pragma unroll
        for (int off = 1; off < 32; off <<= 1) {
            float n = __shfl_up_sync(0xffffffffu, v, off);
            if (lane >= off) v += n;
        }
        v += carry;
        carry = __shfl_sync(0xffffffffu, v, 31);
        buf[lane][warp] = v;
        __syncthreads();
        Sb[c * 1024 + tid] = buf[l][r];
        __syncthreads();
    }
    if (lane == 0)
        g_segsum[(b * NSEG + seg) * RR + warp] = carry;
}

// ======================================================================
// K4: out = (gateU*(S+off)) @ out_w + out_b + depthwise_conv3(x)
// TF32 mma: block = 128 tokens x 128 dcols, K=32 (single tile).
// Inline segment offset (k3b fused). 2 CTAs/SM (reg-capped at 128).
// ======================================================================
#define T4_APAD 36
#define T4_BPAD 136
__global__ void __launch_bounds__(256, 2) k4_mma(
    const float* __restrict__ x,
    const float* __restrict__ conv_w,   // (1024 x 3)
    const float* __restrict__ out_w,    // (32 x 1024)
    const float* __restrict__ out_b,    // (1024)
    float* __restrict__ out)
{
    __shared__ unsigned Gs[128 * T4_APAD];  // glob tile (tokens x 32 ranks), tf32
    __shared__ unsigned Ws[32 * T4_BPAD];   // out_w tile (32 ranks x 128 cols), tf32

    const int tid  = threadIdx.x;
    const int bx   = blockIdx.x;            // d tile 0..7
    const int by   = blockIdx.y;            // token tile 0..127
    const int wid  = tid >> 5;
    const int lane = tid & 31;
    const int g    = lane >> 2;
    const int tig  = lane & 3;
    const int warpM = wid >> 2;             // 0..1
    const int warpN = wid & 3;              // 0..3

    const int token0 = by * 128;
    const int d0     = bx * 128;

    // ---- inline segment offset for this tile's single (b, seg) ----
    const int b   = token0 >> 12;
    const int seg = (token0 & (LL - 1)) >> 7;     // SEG = 128
    const int r   = tid & 31;
    float soff = 0.f;
    for (int s = 0; s < seg; s++)
        soff += g_segsum[(b * NSEG + s) * RR + r];

    // ---- build glob tile: glob = gateU * (S_local + soff), cvt to tf32 ----
    #pragma unroll
    for (int i = 0; i < 16; i++) {
        int flat  = tid + i * 256;                // 0..4095 ; rank = tid&31 = r
        int row   = flat >> 5;
        size_t gi = (size_t)(token0 + row) * RR + r;
        float S = g_glob[gi] + soff;
        Gs[row * T4_APAD + r] = f2tf32(g_gateU[gi] * S);
    }
    #pragma unroll
    for (int i = 0; i < 16; i++) {
        int flat = tid + i * 256;                 // 0..4095
        int rr   = flat >> 7;                     // 0..31
        int c    = flat & 127;
        Ws[rr * T4_BPAD + c] = f2tf32(__ldg(out_w + (size_t)rr * DD + d0 + c));
    }
    __syncthreads();

    // ---- mma: 4 k8 steps over K=32 ----
    float acc[4][4][4];
    #pragma unroll
    for (int ma = 0; ma < 4; ma++)
        #pragma unroll
        for (int na = 0; na < 4; na++)
            #pragma unroll
            for (int i = 0; i < 4; i++) acc[ma][na][i] = 0.f;

    #pragma unroll
    for (int ks = 0; ks < 4; ks++) {
        int kb = ks * 8;
        unsigned afr[4][4], bfr[4][2];
        #pragma unroll
        for (int ma = 0; ma < 4; ma++) {
            int r0 = warpM * 64 + ma * 16;
            afr[ma][0] = Gs[(r0 + g)     * T4_APAD + kb + tig];
            afr[ma][1] = Gs[(r0 + g + 8) * T4_APAD + kb + tig];
            afr[ma][2] = Gs[(r0 + g)     * T4_APAD + kb + tig + 4];
            afr[ma][3] = Gs[(r0 + g + 8) * T4_APAD + kb + tig + 4];
        }
        #pragma unroll
        for (int na = 0; na < 4; na++) {
            int c0 = warpN * 32 + na * 8;
            bfr[na][0] = Ws[(kb + tig)     * T4_BPAD + c0 + g];
            bfr[na][1] = Ws[(kb + tig + 4) * T4_BPAD + c0 + g];
        }
        #pragma unroll
        for (int ma = 0; ma < 4; ma++)
            #pragma unroll
            for (int na = 0; na < 4; na++)
                mma_tf32(acc[ma][na], afr[ma], bfr[na]);
    }

    // ---- epilogue: + out_b + depthwise conv3(x), write out ----
    #pragma unroll
    for (int ma = 0; ma < 4; ma++) {
        #pragma unroll
        for (int rh = 0; rh < 2; rh++) {            // row half: g / g+8
            int token = token0 + warpM * 64 + ma * 16 + g + rh * 8;
            int lpos  = token & (LL - 1);
            #pragma unroll
            for (int na = 0; na < 4; na++) {
                int c = d0 + warpN * 32 + na * 8 + tig * 2;
                const float* xr = x + (size_t)token * DD + c;
                float2 xc = *(const float2*)xr;
                float2 xm = (lpos > 0)      ? *(const float2*)(xr - DD) : make_float2(0.f, 0.f);
                float2 xp = (lpos < LL - 1) ? *(const float2*)(xr + DD) : make_float2(0.f, 0.f);
                float a0 = acc[ma][na][rh * 2 + 0];
                float a1 = acc[ma][na][rh * 2 + 1];
                float2 o;
                o.x = a0 + __ldg(out_b + c)
                        + __ldg(conv_w + c * 3 + 0) * xm.x
                        + __ldg(conv_w + c * 3 + 1) * xc.x
                        + __ldg(conv_w + c * 3 + 2) * xp.x;
                o.y = a1 + __ldg(out_b + c + 1)
                        + __ldg(conv_w + (c + 1) * 3 + 0) * xm.y
                        + __ldg(conv_w + (c + 1) * 3 + 1) * xc.y
                        + __ldg(conv_w + (c + 1) * 3 + 2) * xp.y;
                *(float2*)(out + (size_t)token * DD + c) = o;
            }
        }
    }
}

// ======================================================================
extern "C" void kernel_launch(void* const* d_in, const int* in_sizes, int n_in,
                              void* d_out, int out_size)
{
    const float* x       = (const float*)d_in[0];
    const float* gate_w1 = (const float*)d_in[1];
    const float* gate_b1 = (const float*)d_in[2];
    const float* gate_w2 = (const float*)d_in[3];
    const float* gate_b2 = (const float*)d_in[4];
    const float* U_w     = (const float*)d_in[5];
    const float* V_w     = (const float*)d_in[6];
    const float* conv_w  = (const float*)d_in[7];
    const float* out_w   = (const float*)d_in[8];
    const float* out_b   = (const float*)d_in[9];
    float* out = (float*)d_out;

    // K12: h = relu(x@W1+b1) AND UV = x@[Uw|Vw]  (single pass over x)
    k12_tf32<<<dim3(2, MTOK / 64), 256>>>(x, gate_w1, gate_b1, U_w, V_w);
    // K2b: gateU
    k2b_gate<<<MTOK / 16, 256>>>(gate_w2, gate_b2);
    // K3a: segmented cumsum of V (totals to g_segsum)
    k3a_scan<<<BB * NSEG, 1024>>>();
    // K4: out = glob@out_w + bias + conv  (tf32 mma; k3c+k3b fused)
    k4_mma<<<dim3(DD / 128, MTOK / 128), 256>>>(x, conv_w, out_w, out_b, out);
}